// round 6
// baseline (speedup 1.0000x reference)
#include <cuda_runtime.h>
#include <cuda_bf16.h>
#include <math.h>

// ---------------------------------------------------------------------------
// RGCN (2 layers) on GB300.
//   N=50000 nodes, E=640000 edges, R=8, D_IN=128, D_HID=128, D_OUT=64
//
// layer(x, W[R,D,O], root, b):
//   h[n] = b + x[n]@root + sum_e: dst==n  (x[src_e] @ W[et_e]) / cnt[n, et_e]
//
// Strategy:
//   1. counts + 1/cnt once (same for both layers)
//   2. root GEMM with fused bias  -> output buffer (also initializes it)
//   3. big GEMM x @ [W_0|...|W_7] -> xw scratch [N, R*O]
//   4. edge scatter: atomicAdd(out[dst], xw[src, et*O..] * winv[dst*R+et])
//   5. sigmoid in place on final output
// ---------------------------------------------------------------------------

#define NMAX   50000
#define RREL   8

// scratch (allocation-free rule: __device__ globals)
__device__ float g_xw [(size_t)NMAX * 1024];   // 204.8 MB: [N, R*O] transforms
__device__ float g_h1 [(size_t)NMAX * 128];    // 25.6 MB: layer-1 output
__device__ int   g_cnt [NMAX * RREL];
__device__ float g_winv[NMAX * RREL];

// ---------------------------------------------------------------------------
__global__ void zero_int_k(int* p, int n) {
    int i = blockIdx.x * blockDim.x + threadIdx.x;
    if (i < n) p[i] = 0;
}

__global__ void count_edges_k(const int* __restrict__ dst,
                              const int* __restrict__ et,
                              int* __restrict__ cnt, int E) {
    int i = blockIdx.x * blockDim.x + threadIdx.x;
    if (i < E) atomicAdd(&cnt[dst[i] * RREL + et[i]], 1);
}

__global__ void make_winv_k(const int* __restrict__ cnt,
                            float* __restrict__ winv, int n) {
    int i = blockIdx.x * blockDim.x + threadIdx.x;
    if (i < n) {
        int c = cnt[i];
        winv[i] = 1.0f / (float)(c > 1 ? c : 1);
    }
}

// ---------------------------------------------------------------------------
// Tiled fp32 GEMM:  C[M,N] = A[M,K] @ B  (+ bias broadcast over rows)
// B is the relation-stacked weight W[R, K, O] viewed as [K, R*O]:
//   column (r*O + o) of B == W[r, :, o].  A 64-wide column block never
//   crosses a relation boundary (O is 64 or 128), so each block uses a
//   plain row-major [K, O] slab with base  W + r*K*O + o0.
// BM=128, BN=64, BK=16, 256 threads, 8x4 register tile per thread.
// ---------------------------------------------------------------------------
__global__ __launch_bounds__(256, 2)
void gemm_rel_k(const float* __restrict__ A, const float* __restrict__ W,
                const float* __restrict__ bias, float* __restrict__ C,
                int M, int N, int K, int O)
{
    __shared__ float As[16][128];   // transposed A tile: As[k][m]
    __shared__ float Bs[16][64];    // Bs[k][n]

    const int tid      = threadIdx.x;
    const int blockRow = blockIdx.y * 128;
    const int blockCol = blockIdx.x * 64;

    const int r  = blockCol / O;
    const int o0 = blockCol - r * O;
    const float* Bblk = W + (size_t)r * K * O + o0;

    const int ty      = tid >> 4;        // 0..15
    const int tx      = tid & 15;        // 0..15
    const int rowBase = ty * 8;
    const int colBase = tx * 4;

    float acc[8][4];
    #pragma unroll
    for (int i = 0; i < 8; i++)
        #pragma unroll
        for (int j = 0; j < 4; j++) acc[i][j] = 0.0f;

    for (int kt = 0; kt < K; kt += 16) {
        // A tile: 128x16 = 512 float4, 2 per thread, stored transposed
        #pragma unroll
        for (int l = 0; l < 2; l++) {
            int idx = tid + l * 256;            // 0..511
            int ar  = idx >> 2;                 // 0..127
            int ac  = (idx & 3) * 4;            // 0,4,8,12
            int gr  = blockRow + ar;
            float4 v = make_float4(0.f, 0.f, 0.f, 0.f);
            if (gr < M) v = *(const float4*)&A[(size_t)gr * K + kt + ac];
            As[ac + 0][ar] = v.x;
            As[ac + 1][ar] = v.y;
            As[ac + 2][ar] = v.z;
            As[ac + 3][ar] = v.w;
        }
        // B tile: 16x64 = 256 float4, 1 per thread
        {
            int br = tid >> 4;                  // 0..15
            int bc = (tid & 15) * 4;            // 0..60
            *(float4*)&Bs[br][bc] =
                *(const float4*)&Bblk[(size_t)(kt + br) * O + bc];
        }
        __syncthreads();

        #pragma unroll
        for (int k = 0; k < 16; k++) {
            float a[8], b[4];
            *(float4*)&a[0] = *(float4*)&As[k][rowBase];
            *(float4*)&a[4] = *(float4*)&As[k][rowBase + 4];
            *(float4*)&b[0] = *(float4*)&Bs[k][colBase];
            #pragma unroll
            for (int i = 0; i < 8; i++)
                #pragma unroll
                for (int j = 0; j < 4; j++)
                    acc[i][j] += a[i] * b[j];
        }
        __syncthreads();
    }

    // epilogue (float4 stores; bias index stays within the relation slab)
    #pragma unroll
    for (int i = 0; i < 8; i++) {
        int gr = blockRow + rowBase + i;
        if (gr < M) {
            float4 v;
            v.x = acc[i][0]; v.y = acc[i][1]; v.z = acc[i][2]; v.w = acc[i][3];
            if (bias) {
                int bi = o0 + colBase;
                v.x += bias[bi + 0]; v.y += bias[bi + 1];
                v.z += bias[bi + 2]; v.w += bias[bi + 3];
            }
            *(float4*)&C[(size_t)gr * N + blockCol + colBase] = v;
        }
    }
}

// ---------------------------------------------------------------------------
// Edge scatter: one warp per edge, each lane handles V = O/32 floats.
// out[dst, :] += xw[src, et*O : et*O+O] * winv[dst*R + et]
// ---------------------------------------------------------------------------
template <int V>
__global__ __launch_bounds__(256)
void scatter_edges_k(const float* __restrict__ xw,
                     const int* __restrict__ src,
                     const int* __restrict__ dst,
                     const int* __restrict__ et,
                     const float* __restrict__ winv,
                     float* __restrict__ out,
                     int E, int O, int RO)
{
    int e = blockIdx.x * (blockDim.x >> 5) + (threadIdx.x >> 5);
    if (e >= E) return;
    int lane = threadIdx.x & 31;

    int s = src[e];
    int d = dst[e];
    int t = et[e];
    float w = winv[d * RREL + t];

    const float* row  = xw  + (size_t)s * RO + t * O + lane * V;
    float*       orow = out + (size_t)d * O  + lane * V;

    if (V == 4) {
        float4 v = *(const float4*)row;
        atomicAdd(&orow[0], v.x * w);
        atomicAdd(&orow[1], v.y * w);
        atomicAdd(&orow[2], v.z * w);
        atomicAdd(&orow[3], v.w * w);
    } else {
        float2 v = *(const float2*)row;
        atomicAdd(&orow[0], v.x * w);
        atomicAdd(&orow[1], v.y * w);
    }
}

__global__ void sigmoid_k(float* __restrict__ p, int n) {
    int i = blockIdx.x * blockDim.x + threadIdx.x;
    if (i < n) p[i] = 1.0f / (1.0f + expf(-p[i]));
}

// ---------------------------------------------------------------------------
extern "C" void kernel_launch(void* const* d_in, const int* in_sizes, int n_in,
                              void* d_out, int out_size)
{
    const float* x     = (const float*)d_in[0];
    const int*   esrc  = (const int*)  d_in[1];
    const int*   edst  = (const int*)  d_in[2];
    const int*   etyp  = (const int*)  d_in[3];
    const float* W1    = (const float*)d_in[4];
    const float* root1 = (const float*)d_in[5];
    const float* b1    = (const float*)d_in[6];
    const float* W2    = (const float*)d_in[7];
    const float* root2 = (const float*)d_in[8];
    const float* b2    = (const float*)d_in[9];
    float* out = (float*)d_out;

    const int N = in_sizes[0] / 128;   // 50000
    const int E = in_sizes[1];         // 640000
    const int NR = N * RREL;

    float *xw, *h1, *winv;
    int* cnt;
    cudaGetSymbolAddress((void**)&xw,   g_xw);
    cudaGetSymbolAddress((void**)&h1,   g_h1);
    cudaGetSymbolAddress((void**)&cnt,  g_cnt);
    cudaGetSymbolAddress((void**)&winv, g_winv);

    const int T = 256;
    const int gy = (N + 127) / 128;

    // ---- edge-degree normalization (shared by both layers) ----
    zero_int_k  <<<(NR + T - 1) / T, T>>>(cnt, NR);
    count_edges_k<<<(E + T - 1) / T, T>>>(edst, etyp, cnt, E);
    make_winv_k <<<(NR + T - 1) / T, T>>>(cnt, winv, NR);

    // ---- layer 1: D=128 -> O=128 ----
    gemm_rel_k<<<dim3(128 / 64, gy), T>>>(x, root1, b1, h1, N, 128, 128, 128);
    gemm_rel_k<<<dim3(1024 / 64, gy), T>>>(x, W1, nullptr, xw, N, 1024, 128, 128);
    scatter_edges_k<4><<<(E + 7) / 8, T>>>(xw, esrc, edst, etyp, winv, h1,
                                           E, 128, 1024);

    // ---- layer 2: D=128 -> O=64 (writes straight into d_out) ----
    gemm_rel_k<<<dim3(64 / 64, gy), T>>>(h1, root2, b2, out, N, 64, 128, 64);
    gemm_rel_k<<<dim3(512 / 64, gy), T>>>(h1, W2, nullptr, xw, N, 512, 128, 64);
    scatter_edges_k<2><<<(E + 7) / 8, T>>>(xw, esrc, edst, etyp, winv, out,
                                           E, 64, 512);

    // ---- activation ----
    sigmoid_k<<<(out_size + T - 1) / T, T>>>(out, out_size);
}

// round 10
// speedup vs baseline: 1.2999x; 1.2999x over previous
#include <cuda_runtime.h>
#include <cuda_bf16.h>
#include <math.h>
#include <stdint.h>

// ---------------------------------------------------------------------------
// RGCN (2 layers) on GB300.
//   N=50000 nodes, E=640000 edges, R=8, D_IN=128, D_HID=128, D_OUT=64
//
// This round: GEMMs moved to tensor cores via warp-level mma.m16n8k16 with
// 3xBF16 splitting (AhBh + AlBh + AhBl, fp32 accum) for fp32-class accuracy.
// ---------------------------------------------------------------------------

#define NMAX   50000
#define RREL   8
#define AP     136     // bf16 row pitch for A smem (16B-group conflict-free)
#define BP     136     // bf16 row pitch for B smem (n-major)

// scratch (allocation-free rule: __device__ globals)
__device__ float g_xw [(size_t)NMAX * 1024];   // [N, R*O] transforms
__device__ float g_h1 [(size_t)NMAX * 128];    // layer-1 output
__device__ int   g_cnt [NMAX * RREL];
__device__ float g_winv[NMAX * RREL];

// ---------------------------------------------------------------------------
__global__ void zero_int_k(int* p, int n) {
    int i = blockIdx.x * blockDim.x + threadIdx.x;
    if (i < n) p[i] = 0;
}

__global__ void count_edges_k(const int* __restrict__ dst,
                              const int* __restrict__ et,
                              int* __restrict__ cnt, int E) {
    int i = blockIdx.x * blockDim.x + threadIdx.x;
    if (i < E) atomicAdd(&cnt[dst[i] * RREL + et[i]], 1);
}

__global__ void make_winv_k(const int* __restrict__ cnt,
                            float* __restrict__ winv, int n) {
    int i = blockIdx.x * blockDim.x + threadIdx.x;
    if (i < n) {
        int c = cnt[i];
        winv[i] = 1.0f / (float)(c > 1 ? c : 1);
    }
}

// ---------------------------------------------------------------------------
// warp-MMA helpers
// ---------------------------------------------------------------------------
__device__ __forceinline__ void mma16816(float* d, const uint32_t* a,
                                         const uint32_t* b) {
    asm volatile(
        "mma.sync.aligned.m16n8k16.row.col.f32.bf16.bf16.f32 "
        "{%0,%1,%2,%3}, {%4,%5,%6,%7}, {%8,%9}, {%0,%1,%2,%3};"
        : "+f"(d[0]), "+f"(d[1]), "+f"(d[2]), "+f"(d[3])
        : "r"(a[0]), "r"(a[1]), "r"(a[2]), "r"(a[3]),
          "r"(b[0]), "r"(b[1]));
}

__device__ __forceinline__ void ldsm4(uint32_t* r, uint32_t addr) {
    asm volatile(
        "ldmatrix.sync.aligned.m8n8.x4.shared.b16 {%0,%1,%2,%3}, [%4];"
        : "=r"(r[0]), "=r"(r[1]), "=r"(r[2]), "=r"(r[3])
        : "r"(addr));
}

// ---------------------------------------------------------------------------
// Tensor-core GEMM:  C[M, Ntot] = A[M,128] @ B (+bias), 3xBF16 splitting.
// B is the relation-stacked weight W[R,128,O] viewed as [128, R*O]; a 64-wide
// column block (gc = cb*64) lives in slab r = gc/O at offset oo = gc%O.
//
// Block: 256 threads (8 warps, 4x2), BM=128, BN=64, K=128 staged whole.
// A smem: bf16 hi/lo, row-major [128][AP].  B smem: bf16 hi/lo, n-major
// [64][BP] (transposed at load so non-trans ldmatrix yields B fragments).
// Each CTA handles NB consecutive column blocks (reuses staged A).
// ---------------------------------------------------------------------------
__global__ __launch_bounds__(256, 2)
void gemm_tc_k(const float* __restrict__ A, const float* __restrict__ W,
               const float* __restrict__ bias, float* __restrict__ C,
               int M, int Ntot, int O, int NB)
{
    extern __shared__ __nv_bfloat16 smB[];
    __nv_bfloat16* Ah = smB;                       // [128][AP]
    __nv_bfloat16* Al = smB + 128 * AP;
    __nv_bfloat16* Bh = smB + 2 * 128 * AP;        // [64][BP]
    __nv_bfloat16* Bl = Bh + 64 * BP;

    const int tid  = threadIdx.x;
    const int lane = tid & 31;
    const int wid  = tid >> 5;
    const int rowBase = blockIdx.y * 128;

    // ---- stage A once: fp32 -> bf16 hi/lo ----
    for (int i = tid; i < 128 * 32; i += 256) {
        int r  = i >> 5;
        int c4 = (i & 31) << 2;
        float4 v = make_float4(0.f, 0.f, 0.f, 0.f);
        int gr = rowBase + r;
        if (gr < M) v = *(const float4*)&A[(size_t)gr * 128 + c4];
        float f[4] = {v.x, v.y, v.z, v.w};
        union { __nv_bfloat16 b[4]; uint2 u; } ph, pl;
        #pragma unroll
        for (int j = 0; j < 4; j++) {
            __nv_bfloat16 h = __float2bfloat16_rn(f[j]);
            ph.b[j] = h;
            pl.b[j] = __float2bfloat16_rn(f[j] - __bfloat162float(h));
        }
        *(uint2*)&Ah[r * AP + c4] = ph.u;
        *(uint2*)&Al[r * AP + c4] = pl.u;
    }

    // ---- per-warp fragment addresses ----
    const uint32_t sBase = (uint32_t)__cvta_generic_to_shared(smB);
    const int m0 = (wid >> 1) * 32;       // warp row tile (4 warps in M)
    const int n0 = (wid & 1) * 32;        // warp col tile (2 warps in N)

    uint32_t aHaddr[2], aLaddr[2];
    {
        int ar = lane & 15;               // row within m16 tile
        int ac = (lane >> 4) << 3;        // k-col: 0 or 8
        #pragma unroll
        for (int mt = 0; mt < 2; mt++) {
            aHaddr[mt] = sBase +
                (uint32_t)(((m0 + mt * 16 + ar) * AP + ac) * 2);
            aLaddr[mt] = aHaddr[mt] + 128 * AP * 2;
        }
    }
    uint32_t bAddr[4];
    {
        int br = lane & 7;                       // n row within n8 tile
        int bc = ((lane >> 3) & 1) << 3;         // k-col: 0 or 8
        // lanes 0-15 -> Bh (regs 0,1), lanes 16-31 -> Bl (regs 2,3)
        uint32_t reg = (lane < 16) ? (uint32_t)(2 * 128 * AP)
                                   : (uint32_t)(2 * 128 * AP + 64 * BP);
        #pragma unroll
        for (int nt = 0; nt < 4; nt++)
            bAddr[nt] = sBase + (reg + (n0 + nt * 8 + br) * BP + bc) * 2;
    }

    const int g  = lane >> 2;
    const int t2 = (lane & 3) << 1;

    for (int cbi = 0; cbi < NB; cbi++) {
        const int gc  = (blockIdx.x * NB + cbi) * 64;
        const int rel = gc / O;
        const int oo  = gc - rel * O;
        const float* Bsl = W + (size_t)rel * 128 * O + oo;

        // ---- stage B: fp32 [k][n] -> bf16 hi/lo n-major [n][k] ----
        for (int i = tid; i < 64 * 128; i += 256) {
            int k = i >> 6, n = i & 63;
            float v = Bsl[(size_t)k * O + n];
            __nv_bfloat16 h = __float2bfloat16_rn(v);
            Bh[n * BP + k] = h;
            Bl[n * BP + k] = __float2bfloat16_rn(v - __bfloat162float(h));
        }
        __syncthreads();

        float acc[2][4][4];
        #pragma unroll
        for (int mt = 0; mt < 2; mt++)
            #pragma unroll
            for (int nt = 0; nt < 4; nt++)
                #pragma unroll
                for (int j = 0; j < 4; j++) acc[mt][nt][j] = 0.f;

        #pragma unroll
        for (int ks = 0; ks < 8; ks++) {
            const uint32_t ko = ks * 32;   // 16 bf16 * 2 bytes
            uint32_t ah[2][4], al[2][4], bb[4][4];
            #pragma unroll
            for (int mt = 0; mt < 2; mt++) {
                ldsm4(ah[mt], aHaddr[mt] + ko);
                ldsm4(al[mt], aLaddr[mt] + ko);
            }
            #pragma unroll
            for (int nt = 0; nt < 4; nt++)
                ldsm4(bb[nt], bAddr[nt] + ko);   // {bh0,bh1,bl0,bl1}
            #pragma unroll
            for (int mt = 0; mt < 2; mt++)
                #pragma unroll
                for (int nt = 0; nt < 4; nt++) {
                    mma16816(acc[mt][nt], ah[mt], &bb[nt][0]); // Ah*Bh
                    mma16816(acc[mt][nt], al[mt], &bb[nt][0]); // Al*Bh
                    mma16816(acc[mt][nt], ah[mt], &bb[nt][2]); // Ah*Bl
                }
        }

        // ---- epilogue ----
        #pragma unroll
        for (int mt = 0; mt < 2; mt++) {
            int r0 = rowBase + m0 + mt * 16 + g;
            #pragma unroll
            for (int nt = 0; nt < 4; nt++) {
                int col = gc + n0 + nt * 8 + t2;
                float bx = 0.f, by = 0.f;
                if (bias) {
                    int bi = oo + n0 + nt * 8 + t2;
                    bx = bias[bi]; by = bias[bi + 1];
                }
                if (r0 < M) {
                    float2 v = make_float2(acc[mt][nt][0] + bx,
                                           acc[mt][nt][1] + by);
                    *(float2*)&C[(size_t)r0 * Ntot + col] = v;
                }
                if (r0 + 8 < M) {
                    float2 v = make_float2(acc[mt][nt][2] + bx,
                                           acc[mt][nt][3] + by);
                    *(float2*)&C[(size_t)(r0 + 8) * Ntot + col] = v;
                }
            }
        }
        __syncthreads();   // Bs fully consumed before next col-block staging
    }
}

// ---------------------------------------------------------------------------
// Edge scatter: one warp per edge, each lane handles V = O/32 floats.
// out[dst, :] += xw[src, et*O : et*O+O] * winv[dst*R + et]
// ---------------------------------------------------------------------------
template <int V>
__global__ __launch_bounds__(256)
void scatter_edges_k(const float* __restrict__ xw,
                     const int* __restrict__ src,
                     const int* __restrict__ dst,
                     const int* __restrict__ et,
                     const float* __restrict__ winv,
                     float* __restrict__ out,
                     int E, int O, int RO)
{
    int e = blockIdx.x * (blockDim.x >> 5) + (threadIdx.x >> 5);
    if (e >= E) return;
    int lane = threadIdx.x & 31;

    int s = src[e];
    int d = dst[e];
    int t = et[e];
    float w = winv[d * RREL + t];

    const float* row  = xw  + (size_t)s * RO + t * O + lane * V;
    float*       orow = out + (size_t)d * O  + lane * V;

    if (V == 4) {
        float4 v = *(const float4*)row;
        atomicAdd(&orow[0], v.x * w);
        atomicAdd(&orow[1], v.y * w);
        atomicAdd(&orow[2], v.z * w);
        atomicAdd(&orow[3], v.w * w);
    } else {
        float2 v = *(const float2*)row;
        atomicAdd(&orow[0], v.x * w);
        atomicAdd(&orow[1], v.y * w);
    }
}

__global__ void sigmoid_k(float* __restrict__ p, int n) {
    int i = blockIdx.x * blockDim.x + threadIdx.x;
    if (i < n) p[i] = 1.0f / (1.0f + expf(-p[i]));
}

// ---------------------------------------------------------------------------
extern "C" void kernel_launch(void* const* d_in, const int* in_sizes, int n_in,
                              void* d_out, int out_size)
{
    const float* x     = (const float*)d_in[0];
    const int*   esrc  = (const int*)  d_in[1];
    const int*   edst  = (const int*)  d_in[2];
    const int*   etyp  = (const int*)  d_in[3];
    const float* W1    = (const float*)d_in[4];
    const float* root1 = (const float*)d_in[5];
    const float* b1    = (const float*)d_in[6];
    const float* W2    = (const float*)d_in[7];
    const float* root2 = (const float*)d_in[8];
    const float* b2    = (const float*)d_in[9];
    float* out = (float*)d_out;

    const int N  = in_sizes[0] / 128;   // 50000
    const int E  = in_sizes[1];         // 640000
    const int NR = N * RREL;

    float *xw, *h1, *winv;
    int* cnt;
    cudaGetSymbolAddress((void**)&xw,   g_xw);
    cudaGetSymbolAddress((void**)&h1,   g_h1);
    cudaGetSymbolAddress((void**)&cnt,  g_cnt);
    cudaGetSymbolAddress((void**)&winv, g_winv);

    const int T  = 256;
    const int gy = (N + 127) / 128;

    const int SMEM = (2 * 128 * AP + 2 * 64 * BP) * (int)sizeof(__nv_bfloat16);
    cudaFuncSetAttribute(gemm_tc_k,
                         cudaFuncAttributeMaxDynamicSharedMemorySize, SMEM);

    // ---- edge-degree normalization (shared by both layers) ----
    zero_int_k   <<<(NR + T - 1) / T, T>>>(cnt, NR);
    count_edges_k<<<(E + T - 1) / T, T>>>(edst, etyp, cnt, E);
    make_winv_k  <<<(NR + T - 1) / T, T>>>(cnt, winv, NR);

    // ---- layer 1: D=128 -> O=128 ----
    gemm_tc_k<<<dim3(1, gy), T, SMEM>>>(x, root1, b1, h1, N, 128, 128, 2);
    gemm_tc_k<<<dim3(4, gy), T, SMEM>>>(x, W1, nullptr, xw, N, 1024, 128, 4);
    scatter_edges_k<4><<<(E + 7) / 8, T>>>(xw, esrc, edst, etyp, winv, h1,
                                           E, 128, 1024);

    // ---- layer 2: D=128 -> O=64 (writes straight into d_out) ----
    gemm_tc_k<<<dim3(1, gy), T, SMEM>>>(h1, root2, b2, out, N, 64, 64, 1);
    gemm_tc_k<<<dim3(2, gy), T, SMEM>>>(h1, W2, nullptr, xw, N, 512, 64, 4);
    scatter_edges_k<2><<<(E + 7) / 8, T>>>(xw, esrc, edst, etyp, winv, out,
                                           E, 64, 512);

    // ---- activation ----
    sigmoid_k<<<(out_size + T - 1) / T, T>>>(out, out_size);
}

// round 12
// speedup vs baseline: 1.6937x; 1.3030x over previous
#include <cuda_runtime.h>
#include <cuda_bf16.h>
#include <math.h>
#include <stdint.h>

// ---------------------------------------------------------------------------
// RGCN (2 layers) on GB300.  N=50000, E=640000, R=8, D 128->128->64.
//
// This round: merged (8 relations + root) tensor-core GEMM per layer,
// operands pre-split to bf16 hi/lo in global (weights pre-transposed),
// cp.async staging overlapped with epilogue.  3xBF16 mma.m16n8k16 core.
// ---------------------------------------------------------------------------

#define NMAX   50000
#define RREL   8
#define NSLAB  9          // 8 relations + root
#define AP     136        // bf16 row pitch, A smem  (stride%32words==4: LDSM-clean)
#define BP     136        // bf16 row pitch, B smem (n-major)

// scratch (allocation-free rule: __device__ globals)
__device__ float         g_xw [(size_t)NMAX * 1024];      // [N, R*O] messages
__device__ float         g_h1 [(size_t)NMAX * 128];       // layer-1 output
__device__ int           g_cnt [NMAX * RREL];
__device__ float         g_winv[NMAX * RREL];
__device__ __nv_bfloat16 g_ah [(size_t)NMAX * 128];       // A hi
__device__ __nv_bfloat16 g_al [(size_t)NMAX * 128];       // A lo
__device__ __nv_bfloat16 g_bh [NSLAB * 128 * 128];        // Bt hi  [9*O][128]
__device__ __nv_bfloat16 g_bl [NSLAB * 128 * 128];        // Bt lo

// ---------------------------------------------------------------------------
__global__ void zero_int_k(int* p, int n) {
    int i = blockIdx.x * blockDim.x + threadIdx.x;
    if (i < n) p[i] = 0;
}

__global__ void count_edges_k(const int* __restrict__ dst,
                              const int* __restrict__ et,
                              int* __restrict__ cnt, int E) {
    int i = blockIdx.x * blockDim.x + threadIdx.x;
    if (i < E) atomicAdd(&cnt[dst[i] * RREL + et[i]], 1);
}

__global__ void make_winv_k(const int* __restrict__ cnt,
                            float* __restrict__ winv, int n) {
    int i = blockIdx.x * blockDim.x + threadIdx.x;
    if (i < n) {
        int c = cnt[i];
        winv[i] = 1.0f / (float)(c > 1 ? c : 1);
    }
}

// fp32 -> bf16 hi/lo split, float4-vectorized (n4 = total/4)
__global__ void split_f32_k(const float* __restrict__ X,
                            __nv_bfloat16* __restrict__ H,
                            __nv_bfloat16* __restrict__ L, int n4)
{
    int i = blockIdx.x * blockDim.x + threadIdx.x;
    if (i >= n4) return;
    float4 v = ((const float4*)X)[i];
    float f[4] = {v.x, v.y, v.z, v.w};
    union { __nv_bfloat16 b[4]; uint2 u; } ph, pl;
    #pragma unroll
    for (int j = 0; j < 4; j++) {
        __nv_bfloat16 h = __float2bfloat16_rn(f[j]);
        ph.b[j] = h;
        pl.b[j] = __float2bfloat16_rn(f[j] - __bfloat162float(h));
    }
    ((uint2*)H)[i] = ph.u;
    ((uint2*)L)[i] = pl.u;
}

// pack W[8,128,O] + root[128,O] -> Bt hi/lo, n-major [9*O][128]
__global__ void pack_w_k(const float* __restrict__ W,
                         const float* __restrict__ root,
                         __nv_bfloat16* __restrict__ Bh,
                         __nv_bfloat16* __restrict__ Bl, int O)
{
    int idx = blockIdx.x * blockDim.x + threadIdx.x;
    if (idx >= NSLAB * O * 128) return;
    int k    = idx & 127;
    int row  = idx >> 7;          // slab*O + n
    int slab = row / O;
    int n    = row - slab * O;
    float v = (slab < RREL) ? W[((size_t)slab * 128 + k) * O + n]
                            : root[(size_t)k * O + n];
    __nv_bfloat16 h = __float2bfloat16_rn(v);
    Bh[idx] = h;
    Bl[idx] = __float2bfloat16_rn(v - __bfloat162float(h));
}

// ---------------------------------------------------------------------------
// warp-MMA helpers
// ---------------------------------------------------------------------------
__device__ __forceinline__ void mma16816(float* d, const uint32_t* a,
                                         const uint32_t* b) {
    asm volatile(
        "mma.sync.aligned.m16n8k16.row.col.f32.bf16.bf16.f32 "
        "{%0,%1,%2,%3}, {%4,%5,%6,%7}, {%8,%9}, {%0,%1,%2,%3};"
        : "+f"(d[0]), "+f"(d[1]), "+f"(d[2]), "+f"(d[3])
        : "r"(a[0]), "r"(a[1]), "r"(a[2]), "r"(a[3]),
          "r"(b[0]), "r"(b[1]));
}

__device__ __forceinline__ void ldsm4(uint32_t* r, uint32_t addr) {
    asm volatile(
        "ldmatrix.sync.aligned.m8n8.x4.shared.b16 {%0,%1,%2,%3}, [%4];"
        : "=r"(r[0]), "=r"(r[1]), "=r"(r[2]), "=r"(r[3])
        : "r"(addr));
}

__device__ __forceinline__ void cpa16(uint32_t dst, const void* src, bool p) {
    int sz = p ? 16 : 0;
    asm volatile("cp.async.cg.shared.global [%0], [%1], 16, %2;"
                 :: "r"(dst), "l"(src), "r"(sz));
}
__device__ __forceinline__ void cpa_commit() {
    asm volatile("cp.async.commit_group;");
}
__device__ __forceinline__ void cpa_wait0() {
    asm volatile("cp.async.wait_group 0;");
}

// ---------------------------------------------------------------------------
// Merged tensor-core GEMM, 3xBF16 splitting.
//   A hi/lo: [M,128] bf16 (pre-split).  Bt hi/lo: [9*O][128] bf16 n-major.
//   columns [0, 8*O)   -> Cxw (pitch 8*O), no bias
//   columns [8*O, 9*O) -> Cr  (pitch O),  + bias
// Block: 256 thr (8 warps 4x2), BM=128, BN=64, K=128 whole, NB col-blocks.
// ---------------------------------------------------------------------------
__global__ __launch_bounds__(256, 2)
void gemm_tc2_k(const __nv_bfloat16* __restrict__ Agh,
                const __nv_bfloat16* __restrict__ Agl,
                const __nv_bfloat16* __restrict__ Bth,
                const __nv_bfloat16* __restrict__ Btl,
                const float* __restrict__ bias,
                float* __restrict__ Cxw, float* __restrict__ Cr,
                int M, int O, int NB)
{
    extern __shared__ __nv_bfloat16 smB[];
    const int tid  = threadIdx.x;
    const int lane = tid & 31;
    const int wid  = tid >> 5;
    const int rowBase = blockIdx.y * 128;

    const uint32_t sBase = (uint32_t)__cvta_generic_to_shared(smB);
    const uint32_t sAh = sBase;
    const uint32_t sAl = sBase + 128 * AP * 2;
    const uint32_t sBh = sBase + 2 * 128 * AP * 2;
    const uint32_t sBl = sBh + 64 * BP * 2;

    // ---- stage A (cp.async): 128 rows x 256B, hi+lo ----
    #pragma unroll
    for (int l = 0; l < 8; l++) {
        int i = tid + l * 256;            // 0..2047
        int r = i >> 4, c = i & 15;       // row, 16B chunk
        int gr = rowBase + r;
        bool ok = gr < M;
        size_t go = (size_t)(ok ? gr : 0) * 128 + c * 8;
        uint32_t so = (uint32_t)(r * AP * 2 + c * 16);
        cpa16(sAh + so, Agh + go, ok);
        cpa16(sAl + so, Agl + go, ok);
    }
    // ---- stage B block 0 ----
    {
        int gcol0 = blockIdx.x * NB * 64;
        #pragma unroll
        for (int l = 0; l < 4; l++) {
            int i = tid + l * 256;        // 0..1023
            int n = i >> 4, c = i & 15;
            size_t go = (size_t)(gcol0 + n) * 128 + c * 8;
            uint32_t so = (uint32_t)(n * BP * 2 + c * 16);
            cpa16(sBh + so, Bth + go, true);
            cpa16(sBl + so, Btl + go, true);
        }
    }
    cpa_commit();

    // ---- per-warp fragment addresses ----
    const int m0 = (wid >> 1) * 32;
    const int n0 = (wid & 1) * 32;
    uint32_t aHaddr[2], aLaddr[2];
    {
        int ar = lane & 15;
        int ac = (lane >> 4) << 3;
        #pragma unroll
        for (int mt = 0; mt < 2; mt++) {
            aHaddr[mt] = sAh + (uint32_t)(((m0 + mt * 16 + ar) * AP + ac) * 2);
            aLaddr[mt] = aHaddr[mt] + 128 * AP * 2;
        }
    }
    uint32_t bAddr[4];
    {
        int br = lane & 7;
        int bc = ((lane >> 3) & 1) << 3;
        uint32_t base = (lane < 16) ? sBh : sBl;   // lane-split hi/lo trick
        #pragma unroll
        for (int nt = 0; nt < 4; nt++)
            bAddr[nt] = base + (uint32_t)(((n0 + nt * 8 + br) * BP + bc) * 2);
    }
    const int g  = lane >> 2;
    const int t2 = (lane & 3) << 1;

    for (int cbi = 0; cbi < NB; cbi++) {
        cpa_wait0();
        __syncthreads();

        float acc[2][4][4];
        #pragma unroll
        for (int mt = 0; mt < 2; mt++)
            #pragma unroll
            for (int nt = 0; nt < 4; nt++)
                #pragma unroll
                for (int j = 0; j < 4; j++) acc[mt][nt][j] = 0.f;

        #pragma unroll
        for (int ks = 0; ks < 8; ks++) {
            const uint32_t ko = ks * 32;
            uint32_t ah[2][4], al[2][4], bb[4][4];
            #pragma unroll
            for (int mt = 0; mt < 2; mt++) {
                ldsm4(ah[mt], aHaddr[mt] + ko);
                ldsm4(al[mt], aLaddr[mt] + ko);
            }
            #pragma unroll
            for (int nt = 0; nt < 4; nt++)
                ldsm4(bb[nt], bAddr[nt] + ko);     // {bh0,bh1,bl0,bl1}
            #pragma unroll
            for (int mt = 0; mt < 2; mt++)
                #pragma unroll
                for (int nt = 0; nt < 4; nt++) {
                    mma16816(acc[mt][nt], ah[mt], &bb[nt][0]); // Ah*Bh
                    mma16816(acc[mt][nt], al[mt], &bb[nt][0]); // Al*Bh
                    mma16816(acc[mt][nt], ah[mt], &bb[nt][2]); // Ah*Bl
                }
        }

        __syncthreads();   // all warps done reading B smem

        // prefetch next col-block's B, overlapped with epilogue
        if (cbi + 1 < NB) {
            int gcoln = (blockIdx.x * NB + cbi + 1) * 64;
            #pragma unroll
            for (int l = 0; l < 4; l++) {
                int i = tid + l * 256;
                int n = i >> 4, c = i & 15;
                size_t go = (size_t)(gcoln + n) * 128 + c * 8;
                uint32_t so = (uint32_t)(n * BP * 2 + c * 16);
                cpa16(sBh + so, Bth + go, true);
                cpa16(sBl + so, Btl + go, true);
            }
        }
        cpa_commit();

        // ---- epilogue: route slab<8 -> Cxw, slab==8 -> Cr (+bias) ----
        const int gcol = (blockIdx.x * NB + cbi) * 64;
        const int slab = gcol / O;
        const int oo   = gcol - slab * O;
        const bool isRoot = (slab == RREL);

        #pragma unroll
        for (int mt = 0; mt < 2; mt++) {
            int r0 = rowBase + m0 + mt * 16 + g;
            #pragma unroll
            for (int nt = 0; nt < 4; nt++) {
                int cib = n0 + nt * 8 + t2;        // col in 64-block
                float bx = 0.f, by = 0.f;
                float* p0;
                if (isRoot) {
                    bx = bias[oo + cib]; by = bias[oo + cib + 1];
                    p0 = Cr + (size_t)r0 * O + oo + cib;
                } else {
                    p0 = Cxw + (size_t)r0 * (RREL * O) + slab * O + oo + cib;
                }
                size_t pitch8 = (size_t)8 * (isRoot ? O : RREL * O);
                if (r0 < M)
                    *(float2*)p0 = make_float2(acc[mt][nt][0] + bx,
                                               acc[mt][nt][1] + by);
                if (r0 + 8 < M)
                    *(float2*)(p0 + pitch8) = make_float2(acc[mt][nt][2] + bx,
                                                          acc[mt][nt][3] + by);
            }
        }
    }
}

// ---------------------------------------------------------------------------
// Edge scatter: one warp per edge, each lane handles V = O/32 floats.
// ---------------------------------------------------------------------------
template <int V>
__global__ __launch_bounds__(256)
void scatter_edges_k(const float* __restrict__ xw,
                     const int* __restrict__ src,
                     const int* __restrict__ dst,
                     const int* __restrict__ et,
                     const float* __restrict__ winv,
                     float* __restrict__ out,
                     int E, int O, int RO)
{
    int e = blockIdx.x * (blockDim.x >> 5) + (threadIdx.x >> 5);
    if (e >= E) return;
    int lane = threadIdx.x & 31;

    int s = src[e], d = dst[e], t = et[e];
    float w = winv[d * RREL + t];

    const float* row  = xw  + (size_t)s * RO + t * O + lane * V;
    float*       orow = out + (size_t)d * O  + lane * V;

    if (V == 4) {
        float4 v = *(const float4*)row;
        atomicAdd(&orow[0], v.x * w);
        atomicAdd(&orow[1], v.y * w);
        atomicAdd(&orow[2], v.z * w);
        atomicAdd(&orow[3], v.w * w);
    } else {
        float2 v = *(const float2*)row;
        atomicAdd(&orow[0], v.x * w);
        atomicAdd(&orow[1], v.y * w);
    }
}

__global__ void sigmoid_k(float* __restrict__ p, int n) {
    int i = blockIdx.x * blockDim.x + threadIdx.x;
    if (i < n) p[i] = 1.0f / (1.0f + expf(-p[i]));
}

// ---------------------------------------------------------------------------
extern "C" void kernel_launch(void* const* d_in, const int* in_sizes, int n_in,
                              void* d_out, int out_size)
{
    const float* x     = (const float*)d_in[0];
    const int*   esrc  = (const int*)  d_in[1];
    const int*   edst  = (const int*)  d_in[2];
    const int*   etyp  = (const int*)  d_in[3];
    const float* W1    = (const float*)d_in[4];
    const float* root1 = (const float*)d_in[5];
    const float* b1    = (const float*)d_in[6];
    const float* W2    = (const float*)d_in[7];
    const float* root2 = (const float*)d_in[8];
    const float* b2    = (const float*)d_in[9];
    float* out = (float*)d_out;

    const int N  = in_sizes[0] / 128;   // 50000
    const int E  = in_sizes[1];         // 640000
    const int NR = N * RREL;

    float *xw, *h1, *winv;
    int* cnt;
    __nv_bfloat16 *ah, *al, *bh, *bl;
    cudaGetSymbolAddress((void**)&xw,   g_xw);
    cudaGetSymbolAddress((void**)&h1,   g_h1);
    cudaGetSymbolAddress((void**)&cnt,  g_cnt);
    cudaGetSymbolAddress((void**)&winv, g_winv);
    cudaGetSymbolAddress((void**)&ah,   g_ah);
    cudaGetSymbolAddress((void**)&al,   g_al);
    cudaGetSymbolAddress((void**)&bh,   g_bh);
    cudaGetSymbolAddress((void**)&bl,   g_bl);

    const int T  = 256;
    const int gy = (N + 127) / 128;
    const int n4 = N * 32;              // float4 count of [N,128]

    const int SMEM = (2 * 128 * AP + 2 * 64 * BP) * (int)sizeof(__nv_bfloat16);
    cudaFuncSetAttribute(gemm_tc2_k,
                         cudaFuncAttributeMaxDynamicSharedMemorySize, SMEM);

    // ---- edge-degree normalization (shared by both layers) ----
    zero_int_k   <<<(NR + T - 1) / T, T>>>(cnt, NR);
    count_edges_k<<<(E + T - 1) / T, T>>>(edst, etyp, cnt, E);
    make_winv_k  <<<(NR + T - 1) / T, T>>>(cnt, winv, NR);

    // ---- layer 1: D=128 -> O=128 (merged 8 rel + root, 18 col-blocks) ----
    split_f32_k<<<(n4 + T - 1) / T, T>>>(x, ah, al, n4);
    pack_w_k  <<<(NSLAB * 128 * 128 + T - 1) / T, T>>>(W1, root1, bh, bl, 128);
    gemm_tc2_k<<<dim3(3, gy), T, SMEM>>>(ah, al, bh, bl, b1, xw, h1, N, 128, 6);
    scatter_edges_k<4><<<(E + 7) / 8, T>>>(xw, esrc, edst, etyp, winv, h1,
                                           E, 128, 1024);

    // ---- layer 2: D=128 -> O=64 (9 col-blocks, root -> d_out) ----
    split_f32_k<<<(n4 + T - 1) / T, T>>>(h1, ah, al, n4);
    pack_w_k  <<<(NSLAB * 64 * 128 + T - 1) / T, T>>>(W2, root2, bh, bl, 64);
    gemm_tc2_k<<<dim3(3, gy), T, SMEM>>>(ah, al, bh, bl, b2, xw, out, N, 64, 3);
    scatter_edges_k<2><<<(E + 7) / 8, T>>>(xw, esrc, edst, etyp, winv, out,
                                           E, 64, 512);

    // ---- activation ----
    sigmoid_k<<<(out_size + T - 1) / T, T>>>(out, out_size);
}

// round 14
// speedup vs baseline: 1.8512x; 1.0930x over previous
#include <cuda_runtime.h>
#include <cuda_bf16.h>
#include <math.h>
#include <stdint.h>

// ---------------------------------------------------------------------------
// RGCN (2 layers) on GB300.  N=50000, E=640000, R=8, D 128->128->64.
//
// This round: scatter atomics vectorized (red.global.add.v4/v2.f32 -> 4x
// fewer L2-atomic ops), winv folded into scatter, fast sigmoid.
// GEMM core (3xBF16 mma.m16n8k16, merged 9-slab, cp.async) unchanged.
// ---------------------------------------------------------------------------

#define NMAX   50000
#define RREL   8
#define NSLAB  9          // 8 relations + root
#define AP     136        // bf16 row pitch, A smem
#define BP     136        // bf16 row pitch, B smem (n-major)

// scratch (allocation-free rule: __device__ globals)
__device__ float         g_xw [(size_t)NMAX * 1024];      // [N, R*O] messages
__device__ float         g_h1 [(size_t)NMAX * 128];       // layer-1 output
__device__ int           g_cnt [NMAX * RREL];
__device__ __nv_bfloat16 g_ah [(size_t)NMAX * 128];       // A hi
__device__ __nv_bfloat16 g_al [(size_t)NMAX * 128];       // A lo
__device__ __nv_bfloat16 g_bh [NSLAB * 128 * 128];        // Bt hi  [9*O][128]
__device__ __nv_bfloat16 g_bl [NSLAB * 128 * 128];        // Bt lo

// ---------------------------------------------------------------------------
__global__ void zero_int_k(int* p, int n) {
    int i = blockIdx.x * blockDim.x + threadIdx.x;
    if (i < n) p[i] = 0;
}

__global__ void count_edges_k(const int* __restrict__ dst,
                              const int* __restrict__ et,
                              int* __restrict__ cnt, int E) {
    int i = blockIdx.x * blockDim.x + threadIdx.x;
    if (i < E) atomicAdd(&cnt[dst[i] * RREL + et[i]], 1);
}

// fp32 -> bf16 hi/lo split, float4-vectorized (n4 = total/4)
__global__ void split_f32_k(const float* __restrict__ X,
                            __nv_bfloat16* __restrict__ H,
                            __nv_bfloat16* __restrict__ L, int n4)
{
    int i = blockIdx.x * blockDim.x + threadIdx.x;
    if (i >= n4) return;
    float4 v = ((const float4*)X)[i];
    float f[4] = {v.x, v.y, v.z, v.w};
    union { __nv_bfloat16 b[4]; uint2 u; } ph, pl;
    #pragma unroll
    for (int j = 0; j < 4; j++) {
        __nv_bfloat16 h = __float2bfloat16_rn(f[j]);
        ph.b[j] = h;
        pl.b[j] = __float2bfloat16_rn(f[j] - __bfloat162float(h));
    }
    ((uint2*)H)[i] = ph.u;
    ((uint2*)L)[i] = pl.u;
}

// pack W[8,128,O] + root[128,O] -> Bt hi/lo, n-major [9*O][128]
__global__ void pack_w_k(const float* __restrict__ W,
                         const float* __restrict__ root,
                         __nv_bfloat16* __restrict__ Bh,
                         __nv_bfloat16* __restrict__ Bl, int O)
{
    int idx = blockIdx.x * blockDim.x + threadIdx.x;
    if (idx >= NSLAB * O * 128) return;
    int k    = idx & 127;
    int row  = idx >> 7;          // slab*O + n
    int slab = row / O;
    int n    = row - slab * O;
    float v = (slab < RREL) ? W[((size_t)slab * 128 + k) * O + n]
                            : root[(size_t)k * O + n];
    __nv_bfloat16 h = __float2bfloat16_rn(v);
    Bh[idx] = h;
    Bl[idx] = __float2bfloat16_rn(v - __bfloat162float(h));
}

// ---------------------------------------------------------------------------
// warp-MMA helpers
// ---------------------------------------------------------------------------
__device__ __forceinline__ void mma16816(float* d, const uint32_t* a,
                                         const uint32_t* b) {
    asm volatile(
        "mma.sync.aligned.m16n8k16.row.col.f32.bf16.bf16.f32 "
        "{%0,%1,%2,%3}, {%4,%5,%6,%7}, {%8,%9}, {%0,%1,%2,%3};"
        : "+f"(d[0]), "+f"(d[1]), "+f"(d[2]), "+f"(d[3])
        : "r"(a[0]), "r"(a[1]), "r"(a[2]), "r"(a[3]),
          "r"(b[0]), "r"(b[1]));
}

__device__ __forceinline__ void ldsm4(uint32_t* r, uint32_t addr) {
    asm volatile(
        "ldmatrix.sync.aligned.m8n8.x4.shared.b16 {%0,%1,%2,%3}, [%4];"
        : "=r"(r[0]), "=r"(r[1]), "=r"(r[2]), "=r"(r[3])
        : "r"(addr));
}

__device__ __forceinline__ void cpa16(uint32_t dst, const void* src, bool p) {
    int sz = p ? 16 : 0;
    asm volatile("cp.async.cg.shared.global [%0], [%1], 16, %2;"
                 :: "r"(dst), "l"(src), "r"(sz));
}
__device__ __forceinline__ void cpa_commit() {
    asm volatile("cp.async.commit_group;");
}
__device__ __forceinline__ void cpa_wait0() {
    asm volatile("cp.async.wait_group 0;");
}

// ---------------------------------------------------------------------------
// Merged tensor-core GEMM, 3xBF16 splitting (unchanged core).
// ---------------------------------------------------------------------------
__global__ __launch_bounds__(256, 2)
void gemm_tc2_k(const __nv_bfloat16* __restrict__ Agh,
                const __nv_bfloat16* __restrict__ Agl,
                const __nv_bfloat16* __restrict__ Bth,
                const __nv_bfloat16* __restrict__ Btl,
                const float* __restrict__ bias,
                float* __restrict__ Cxw, float* __restrict__ Cr,
                int M, int O, int NB)
{
    extern __shared__ __nv_bfloat16 smB[];
    const int tid  = threadIdx.x;
    const int lane = tid & 31;
    const int wid  = tid >> 5;
    const int rowBase = blockIdx.y * 128;

    const uint32_t sBase = (uint32_t)__cvta_generic_to_shared(smB);
    const uint32_t sAh = sBase;
    const uint32_t sAl = sBase + 128 * AP * 2;
    const uint32_t sBh = sBase + 2 * 128 * AP * 2;
    const uint32_t sBl = sBh + 64 * BP * 2;

    // ---- stage A (cp.async): 128 rows x 256B, hi+lo ----
    #pragma unroll
    for (int l = 0; l < 8; l++) {
        int i = tid + l * 256;            // 0..2047
        int r = i >> 4, c = i & 15;       // row, 16B chunk
        int gr = rowBase + r;
        bool ok = gr < M;
        size_t go = (size_t)(ok ? gr : 0) * 128 + c * 8;
        uint32_t so = (uint32_t)(r * AP * 2 + c * 16);
        cpa16(sAh + so, Agh + go, ok);
        cpa16(sAl + so, Agl + go, ok);
    }
    // ---- stage B block 0 ----
    {
        int gcol0 = blockIdx.x * NB * 64;
        #pragma unroll
        for (int l = 0; l < 4; l++) {
            int i = tid + l * 256;        // 0..1023
            int n = i >> 4, c = i & 15;
            size_t go = (size_t)(gcol0 + n) * 128 + c * 8;
            uint32_t so = (uint32_t)(n * BP * 2 + c * 16);
            cpa16(sBh + so, Bth + go, true);
            cpa16(sBl + so, Btl + go, true);
        }
    }
    cpa_commit();

    // ---- per-warp fragment addresses ----
    const int m0 = (wid >> 1) * 32;
    const int n0 = (wid & 1) * 32;
    uint32_t aHaddr[2], aLaddr[2];
    {
        int ar = lane & 15;
        int ac = (lane >> 4) << 3;
        #pragma unroll
        for (int mt = 0; mt < 2; mt++) {
            aHaddr[mt] = sAh + (uint32_t)(((m0 + mt * 16 + ar) * AP + ac) * 2);
            aLaddr[mt] = aHaddr[mt] + 128 * AP * 2;
        }
    }
    uint32_t bAddr[4];
    {
        int br = lane & 7;
        int bc = ((lane >> 3) & 1) << 3;
        uint32_t base = (lane < 16) ? sBh : sBl;   // lane-split hi/lo trick
        #pragma unroll
        for (int nt = 0; nt < 4; nt++)
            bAddr[nt] = base + (uint32_t)(((n0 + nt * 8 + br) * BP + bc) * 2);
    }
    const int g  = lane >> 2;
    const int t2 = (lane & 3) << 1;

    for (int cbi = 0; cbi < NB; cbi++) {
        cpa_wait0();
        __syncthreads();

        float acc[2][4][4];
        #pragma unroll
        for (int mt = 0; mt < 2; mt++)
            #pragma unroll
            for (int nt = 0; nt < 4; nt++)
                #pragma unroll
                for (int j = 0; j < 4; j++) acc[mt][nt][j] = 0.f;

        #pragma unroll
        for (int ks = 0; ks < 8; ks++) {
            const uint32_t ko = ks * 32;
            uint32_t ah[2][4], al[2][4], bb[4][4];
            #pragma unroll
            for (int mt = 0; mt < 2; mt++) {
                ldsm4(ah[mt], aHaddr[mt] + ko);
                ldsm4(al[mt], aLaddr[mt] + ko);
            }
            #pragma unroll
            for (int nt = 0; nt < 4; nt++)
                ldsm4(bb[nt], bAddr[nt] + ko);     // {bh0,bh1,bl0,bl1}
            #pragma unroll
            for (int mt = 0; mt < 2; mt++)
                #pragma unroll
                for (int nt = 0; nt < 4; nt++) {
                    mma16816(acc[mt][nt], ah[mt], &bb[nt][0]); // Ah*Bh
                    mma16816(acc[mt][nt], al[mt], &bb[nt][0]); // Al*Bh
                    mma16816(acc[mt][nt], ah[mt], &bb[nt][2]); // Ah*Bl
                }
        }

        __syncthreads();   // all warps done reading B smem

        // prefetch next col-block's B, overlapped with epilogue
        if (cbi + 1 < NB) {
            int gcoln = (blockIdx.x * NB + cbi + 1) * 64;
            #pragma unroll
            for (int l = 0; l < 4; l++) {
                int i = tid + l * 256;
                int n = i >> 4, c = i & 15;
                size_t go = (size_t)(gcoln + n) * 128 + c * 8;
                uint32_t so = (uint32_t)(n * BP * 2 + c * 16);
                cpa16(sBh + so, Bth + go, true);
                cpa16(sBl + so, Btl + go, true);
            }
        }
        cpa_commit();

        // ---- epilogue: route slab<8 -> Cxw, slab==8 -> Cr (+bias) ----
        const int gcol = (blockIdx.x * NB + cbi) * 64;
        const int slab = gcol / O;
        const int oo   = gcol - slab * O;
        const bool isRoot = (slab == RREL);

        #pragma unroll
        for (int mt = 0; mt < 2; mt++) {
            int r0 = rowBase + m0 + mt * 16 + g;
            #pragma unroll
            for (int nt = 0; nt < 4; nt++) {
                int cib = n0 + nt * 8 + t2;        // col in 64-block
                float bx = 0.f, by = 0.f;
                float* p0;
                if (isRoot) {
                    bx = bias[oo + cib]; by = bias[oo + cib + 1];
                    p0 = Cr + (size_t)r0 * O + oo + cib;
                } else {
                    p0 = Cxw + (size_t)r0 * (RREL * O) + slab * O + oo + cib;
                }
                size_t pitch8 = (size_t)8 * (isRoot ? O : RREL * O);
                if (r0 < M)
                    *(float2*)p0 = make_float2(acc[mt][nt][0] + bx,
                                               acc[mt][nt][1] + by);
                if (r0 + 8 < M)
                    *(float2*)(p0 + pitch8) = make_float2(acc[mt][nt][2] + bx,
                                                          acc[mt][nt][3] + by);
            }
        }
    }
}

// ---------------------------------------------------------------------------
// Edge scatter: one warp per edge, lane handles V = O/32 floats.
// Vector reductions (red.global.add.v4/v2.f32): 1 atomic request per 16/8 B.
// winv computed inline from cnt (1 int load + rcp, replaces winv pass).
// ---------------------------------------------------------------------------
template <int V>
__global__ __launch_bounds__(256)
void scatter_edges_k(const float* __restrict__ xw,
                     const int* __restrict__ src,
                     const int* __restrict__ dst,
                     const int* __restrict__ et,
                     const int* __restrict__ cnt,
                     float* __restrict__ out,
                     int E, int O, int RO)
{
    int e = blockIdx.x * (blockDim.x >> 5) + (threadIdx.x >> 5);
    if (e >= E) return;
    int lane = threadIdx.x & 31;

    int s = src[e], d = dst[e], t = et[e];
    int c = cnt[d * RREL + t];
    float w = 1.0f / (float)(c > 1 ? c : 1);

    const float* row  = xw  + (size_t)s * RO + t * O + lane * V;
    float*       orow = out + (size_t)d * O  + lane * V;

    if (V == 4) {
        float4 v = *(const float4*)row;
        asm volatile("red.global.add.v4.f32 [%0], {%1, %2, %3, %4};"
                     :: "l"(orow), "f"(v.x * w), "f"(v.y * w),
                        "f"(v.z * w), "f"(v.w * w)
                     : "memory");
    } else {
        float2 v = *(const float2*)row;
        asm volatile("red.global.add.v2.f32 [%0], {%1, %2};"
                     :: "l"(orow), "f"(v.x * w), "f"(v.y * w)
                     : "memory");
    }
}

__global__ void sigmoid_k(float* __restrict__ p, int n) {
    int i = blockIdx.x * blockDim.x + threadIdx.x;
    if (i < n) p[i] = 1.0f / (1.0f + __expf(-p[i]));
}

// ---------------------------------------------------------------------------
extern "C" void kernel_launch(void* const* d_in, const int* in_sizes, int n_in,
                              void* d_out, int out_size)
{
    const float* x     = (const float*)d_in[0];
    const int*   esrc  = (const int*)  d_in[1];
    const int*   edst  = (const int*)  d_in[2];
    const int*   etyp  = (const int*)  d_in[3];
    const float* W1    = (const float*)d_in[4];
    const float* root1 = (const float*)d_in[5];
    const float* b1    = (const float*)d_in[6];
    const float* W2    = (const float*)d_in[7];
    const float* root2 = (const float*)d_in[8];
    const float* b2    = (const float*)d_in[9];
    float* out = (float*)d_out;

    const int N  = in_sizes[0] / 128;   // 50000
    const int E  = in_sizes[1];         // 640000
    const int NR = N * RREL;

    float *xw, *h1;
    int* cnt;
    __nv_bfloat16 *ah, *al, *bh, *bl;
    cudaGetSymbolAddress((void**)&xw,  g_xw);
    cudaGetSymbolAddress((void**)&h1,  g_h1);
    cudaGetSymbolAddress((void**)&cnt, g_cnt);
    cudaGetSymbolAddress((void**)&ah,  g_ah);
    cudaGetSymbolAddress((void**)&al,  g_al);
    cudaGetSymbolAddress((void**)&bh,  g_bh);
    cudaGetSymbolAddress((void**)&bl,  g_bl);

    const int T  = 256;
    const int gy = (N + 127) / 128;
    const int n4 = N * 32;              // float4 count of [N,128]

    const int SMEM = (2 * 128 * AP + 2 * 64 * BP) * (int)sizeof(__nv_bfloat16);
    cudaFuncSetAttribute(gemm_tc2_k,
                         cudaFuncAttributeMaxDynamicSharedMemorySize, SMEM);

    // ---- edge-degree counts (shared by both layers) ----
    zero_int_k   <<<(NR + T - 1) / T, T>>>(cnt, NR);
    count_edges_k<<<(E + T - 1) / T, T>>>(edst, etyp, cnt, E);

    // ---- layer 1: D=128 -> O=128 (merged 8 rel + root) ----
    split_f32_k<<<(n4 + T - 1) / T, T>>>(x, ah, al, n4);
    pack_w_k  <<<(NSLAB * 128 * 128 + T - 1) / T, T>>>(W1, root1, bh, bl, 128);
    gemm_tc2_k<<<dim3(3, gy), T, SMEM>>>(ah, al, bh, bl, b1, xw, h1, N, 128, 6);
    scatter_edges_k<4><<<(E + 7) / 8, T>>>(xw, esrc, edst, etyp, cnt, h1,
                                           E, 128, 1024);

    // ---- layer 2: D=128 -> O=64 (root -> d_out) ----
    split_f32_k<<<(n4 + T - 1) / T, T>>>(h1, ah, al, n4);
    pack_w_k  <<<(NSLAB * 64 * 128 + T - 1) / T, T>>>(W2, root2, bh, bl, 64);
    gemm_tc2_k<<<dim3(3, gy), T, SMEM>>>(ah, al, bh, bl, b2, xw, out, N, 64, 3);
    scatter_edges_k<2><<<(E + 7) / 8, T>>>(xw, esrc, edst, etyp, cnt, out,
                                           E, 64, 512);

    // ---- activation ----
    sigmoid_k<<<(out_size + T - 1) / T, T>>>(out, out_size);
}